// round 16
// baseline (speedup 1.0000x reference)
#include <cuda_runtime.h>
#include <math.h>
#include <stdint.h>

#define N 4096
#define M 4096
#define D 512

#define BT 128          // tile (rows and cols)
#define KC 64           // K (int8 bytes) per pipeline stage
#define NSTG 4
#define ITERS (D / KC)  // 8
#define ROWB 80         // smem row stride in bytes
#define STAGE_BYTES (2 * BT * ROWB)     // 20480
#define SMEM_DYN (NSTG * STAGE_BYTES)   // 81920
#define NTILES_TOT ((N / BT) * (M / BT))  // 1024
#define NPERS 296                          // persistent CTAs (148 SMs x occ 2)

typedef unsigned long long u64;

// scratch
__device__ __align__(16) int8_t g_ai8[N * D];
__device__ __align__(16) int8_t g_bi8[M * D];
__device__ __align__(16) float g_sa[N];
__device__ __align__(16) float g_sb[M];
__device__ __align__(16) float g_x2[N];
__device__ __align__(16) float g_y2[M];
__device__ __align__(16) float g_part[M / BT][N];
__device__ __align__(16) float g_dlbl[N];
__device__ int g_is64;
__device__ unsigned int g_ticket;

// ---------------- helpers ----------------
__device__ __forceinline__ uint32_t smem_u32(const void* p) {
    uint32_t a;
    asm("{ .reg .u64 t; cvta.to.shared.u64 t, %1; cvt.u32.u64 %0, t; }" : "=r"(a) : "l"(p));
    return a;
}
__device__ __forceinline__ void cp16(uint32_t dst, const void* src) {
    asm volatile("cp.async.cg.shared.global [%0], [%1], 16;" :: "r"(dst), "l"(src) : "memory");
}
__device__ __forceinline__ void cp_commit() { asm volatile("cp.async.commit_group;" ::: "memory"); }
__device__ __forceinline__ void cp_wait2()  { asm volatile("cp.async.wait_group 2;"  ::: "memory"); }
__device__ __forceinline__ float sqa(float x)  { float r; asm("sqrt.approx.f32 %0, %1;" : "=f"(r) : "f"(x)); return r; }
__device__ __forceinline__ float ex2a(float x) { float r; asm("ex2.approx.f32 %0, %1;"  : "=f"(r) : "f"(x)); return r; }

// packed f32x2 (fma.rn.f32x2 + mov.b64, both validated in passing runs)
__device__ __forceinline__ u64 pack2(float x, float y) {
    u64 r; asm("mov.b64 %0, {%1, %2};" : "=l"(r) : "f"(x), "f"(y)); return r;
}
__device__ __forceinline__ void unpack2(u64 v, float& x, float& y) {
    asm("mov.b64 {%0, %1}, %2;" : "=f"(x), "=f"(y) : "l"(v));
}
__device__ __forceinline__ u64 fma2(u64 a, u64 b, u64 c) {
    u64 r; asm("fma.rn.f32x2 %0, %1, %2, %3;" : "=l"(r) : "l"(a), "l"(b), "l"(c)); return r;
}

__device__ __forceinline__ void ldmx4(uint32_t* r, uint32_t a) {
    asm volatile("ldmatrix.sync.aligned.m8n8.x4.shared.b16 {%0,%1,%2,%3}, [%4];"
                 : "=r"(r[0]), "=r"(r[1]), "=r"(r[2]), "=r"(r[3]) : "r"(a));
}
__device__ __forceinline__ void ldmx2(uint32_t* r, uint32_t a) {
    asm volatile("ldmatrix.sync.aligned.m8n8.x2.shared.b16 {%0,%1}, [%2];"
                 : "=r"(r[0]), "=r"(r[1]) : "r"(a));
}
__device__ __forceinline__ void mma32(int* c, const uint32_t* a, const uint32_t* b) {
    asm volatile(
        "mma.sync.aligned.m16n8k32.row.col.s32.s8.s8.s32 "
        "{%0,%1,%2,%3}, {%4,%5,%6,%7}, {%8,%9}, {%0,%1,%2,%3};"
        : "+r"(c[0]), "+r"(c[1]), "+r"(c[2]), "+r"(c[3])
        : "r"(a[0]), "r"(a[1]), "r"(a[2]), "r"(a[3]), "r"(b[0]), "r"(b[1]));
}

// ---------------- kernel 1: fused ticket-reset + label-detect + norms + int8 quant ----------------
__global__ void quant_kernel(const float* __restrict__ feat,
                             const float* __restrict__ feat2,
                             const unsigned int* __restrict__ lw) {
    if (blockIdx.x == 0) {
        if (threadIdx.x == 0) g_ticket = 0u;
        __shared__ int any;
        if (threadIdx.x == 0) any = 0;
        __syncthreads();
        int a = 0;
        for (int i = 1 + 2 * threadIdx.x; i < 2 * N; i += 2 * blockDim.x)
            if (lw[i] != 0u) a = 1;
        if (a) any = 1;
        __syncthreads();
        if (threadIdx.x == 0) g_is64 = (any == 0) ? 1 : 0;
    }

    int wid  = (blockIdx.x * blockDim.x + threadIdx.x) >> 5;
    int lane = threadIdx.x & 31;
    if (wid >= N + M) return;
    const int isA = (wid < N);
    const int row = isA ? wid : wid - N;
    const float* src = isA ? feat + (size_t)row * D : feat2 + (size_t)row * D;

    float4 v[4];
#pragma unroll
    for (int j = 0; j < 4; j++) v[j] = ((const float4*)src)[lane * 4 + j];

    float ss = 0.f, am = 0.f;
#pragma unroll
    for (int j = 0; j < 4; j++) {
        ss += v[j].x * v[j].x + v[j].y * v[j].y + v[j].z * v[j].z + v[j].w * v[j].w;
        am = fmaxf(am, fmaxf(fmaxf(fabsf(v[j].x), fabsf(v[j].y)),
                             fmaxf(fabsf(v[j].z), fabsf(v[j].w))));
    }
#pragma unroll
    for (int off = 16; off; off >>= 1) {
        ss += __shfl_xor_sync(0xffffffffu, ss, off);
        am = fmaxf(am, __shfl_xor_sync(0xffffffffu, am, off));
    }
    const float inv = (am > 0.f) ? (127.0f / am) : 0.f;

    uint32_t words[4];
#pragma unroll
    for (int j = 0; j < 4; j++) {
        int q0 = __float2int_rn(v[j].x * inv);
        int q1 = __float2int_rn(v[j].y * inv);
        int q2 = __float2int_rn(v[j].z * inv);
        int q3 = __float2int_rn(v[j].w * inv);
        q0 = max(-127, min(127, q0)); q1 = max(-127, min(127, q1));
        q2 = max(-127, min(127, q2)); q3 = max(-127, min(127, q3));
        words[j] = (uint32_t)(q0 & 0xFF) | ((uint32_t)(q1 & 0xFF) << 8)
                 | ((uint32_t)(q2 & 0xFF) << 16) | ((uint32_t)(q3 & 0xFF) << 24);
    }
    int8_t* dst = (isA ? g_ai8 : g_bi8) + (size_t)row * D;
    ((uint4*)dst)[lane] = make_uint4(words[0], words[1], words[2], words[3]);

    if (lane == 0) {
        const float sc = am * (1.0f / 127.0f);
        if (isA) { g_x2[row] = ss; g_sa[row] = sc; }
        else     { g_y2[row] = ss; g_sb[row] = sc; }
    }
}

// ---------------- kernel 2: persistent int8 mma GEMM + fused softmax epilogue ----------------
__device__ __forceinline__ void load_stage(int it, int r0, int c0, uint32_t sb, int tid) {
    const int st  = it & (NSTG - 1);
    const int kc0 = it * KC;
    const uint32_t A = sb + st * STAGE_BYTES;
    const uint32_t B = A + BT * ROWB;
#pragma unroll
    for (int i = 0; i < 2; i++) {       // A: 128 rows x 4 chunks of 16B
        int q = tid + 256 * i;
        int row = q >> 2, g = q & 3;
        cp16(A + row * ROWB + g * 16, &g_ai8[(size_t)(r0 + row) * D + kc0 + g * 16]);
    }
#pragma unroll
    for (int i = 0; i < 2; i++) {       // B: 128 cols x 4 chunks
        int q = tid + 256 * i;
        int col = q >> 2, g = q & 3;
        cp16(B + col * ROWB + g * 16, &g_bi8[(size_t)(c0 + col) * D + kc0 + g * 16]);
    }
}

__global__ __launch_bounds__(256, 2)
void gemm_kernel(const void* __restrict__ labels,
                 const float* __restrict__ temp) {
    extern __shared__ char dyn[];
    __shared__ __align__(16) float x2s[BT], y2s[BT], sas[BT], sbs[BT];
    __shared__ int   lbs[BT];
    __shared__ float rowsum[BT][4];
    __shared__ int   tileSh;

    const uint32_t sb = smem_u32(dyn);
    const int tid  = threadIdx.x;
    const int wid  = tid >> 5;
    const int lane = tid & 31;
    const int wm   = wid & 1;
    const int wn   = wid >> 1;
    const int g    = lane >> 2;
    const int t    = lane & 3;

    const float invT = 1.0f / temp[0];
    const float cexp = -invT * 1.4426950408889634f;  // -log2(e)/T
    const u64 zerop = pack2(0.f, 0.f);
    const u64 onep  = pack2(1.f, 1.f);

    const uint32_t aoff = (uint32_t)((wm * 64 + (lane & 15)) * ROWB + ((lane >> 4) * 16));
    const uint32_t boff = (uint32_t)(BT * ROWB + (wn * 32 + (lane & 7)) * ROWB + (((lane >> 3) & 1) * 16));

    for (;;) {
        // ---- dynamic ticket: grab next tile ----
        if (tid == 0) tileSh = (int)atomicAdd(&g_ticket, 1u);
        __syncthreads();
        const int tile = tileSh;
        if (tile >= NTILES_TOT) break;
        const int r0 = (tile >> 5) * BT;
        const int c0 = (tile & 31) * BT;

        // ---- tile metadata ----
        if (tid < BT) {
            x2s[tid] = g_x2[r0 + tid];
            y2s[tid] = g_y2[c0 + tid];
            sas[tid] = g_sa[r0 + tid];
            sbs[tid] = g_sb[c0 + tid];
            long long l = g_is64 ? ((const long long*)labels)[r0 + tid]
                                 : (long long)((const int*)labels)[r0 + tid];
            if (l < 0) l = 0; if (l >= M) l = M - 1;
            lbs[tid] = (int)l;
        }

        int c[4][4][4];
#pragma unroll
        for (int mt = 0; mt < 4; mt++)
#pragma unroll
            for (int nt = 0; nt < 4; nt++)
#pragma unroll
                for (int j = 0; j < 4; j++) c[mt][nt][j] = 0;

        for (int p = 0; p < NSTG - 1; p++) { load_stage(p, r0, c0, sb, tid); cp_commit(); }

        for (int it = 0; it < ITERS; ++it) {
            cp_wait2();
            __syncthreads();
            const uint32_t stg = sb + (it & (NSTG - 1)) * STAGE_BYTES;
#pragma unroll
            for (int s = 0; s < 2; s++) {
                const uint32_t ks = s * 32;
                uint32_t af[4][4];
#pragma unroll
                for (int mt = 0; mt < 4; mt++) ldmx4(af[mt], stg + aoff + mt * (16 * ROWB) + ks);
                uint32_t bf[4][2];
#pragma unroll
                for (int nt = 0; nt < 4; nt++) ldmx2(bf[nt], stg + boff + nt * (8 * ROWB) + ks);
#pragma unroll
                for (int mt = 0; mt < 4; mt++)
#pragma unroll
                    for (int nt = 0; nt < 4; nt++) mma32(c[mt][nt], af[mt], bf[nt]);
            }
            if (it + NSTG - 1 < ITERS) load_stage(it + NSTG - 1, r0, c0, sb, tid);
            cp_commit();
        }
        __syncthreads();

        // ---- fused epilogue ----
        u64 esum[4][2];
#pragma unroll
        for (int mt = 0; mt < 4; mt++) { esum[mt][0] = zerop; esum[mt][1] = zerop; }

#pragma unroll
        for (int mt = 0; mt < 4; mt++) {
            const int rlo = wm * 64 + mt * 16 + g;
            const int rhi = rlo + 8;
            const float xlo = x2s[rlo], xhi = x2s[rhi];
            const float slo2 = -2.0f * sas[rlo], shi2 = -2.0f * sas[rhi];
            const u64 xlop = pack2(xlo, xlo), xhip = pack2(xhi, xhi);
            const u64 slo2p = pack2(slo2, slo2), shi2p = pack2(shi2, shi2);
            const int llo = lbs[rlo], lhi = lbs[rhi];
#pragma unroll
            for (int nt = 0; nt < 4; nt++) {
                const int cl = wn * 32 + nt * 8 + t * 2;
                const float2 yv = *(const float2*)(y2s + cl);
                const float2 bv = *(const float2*)(sbs + cl);
                const u64 yp = pack2(yv.x, yv.y);
                const u64 bp = pack2(bv.x, bv.y);
                const int cg0 = c0 + cl, cg1 = cg0 + 1;
                {
                    const u64 sc = fma2(bp, slo2p, zerop);
                    const u64 xy = fma2(yp, onep, xlop);
                    const u64 cp = pack2((float)c[mt][nt][0], (float)c[mt][nt][1]);
                    const u64 d2 = fma2(cp, sc, xy);
                    float d20, d21; unpack2(d2, d20, d21);
                    const float dist0 = sqa(fmaxf(d20, 0.f));
                    const float dist1 = sqa(fmaxf(d21, 0.f));
                    const float e0 = ex2a(dist0 * cexp);
                    const float e1 = ex2a(dist1 * cexp);
                    esum[mt][0] = fma2(pack2(e0, e1), onep, esum[mt][0]);
                    if (cg0 == llo) g_dlbl[r0 + rlo] = dist0;
                    if (cg1 == llo) g_dlbl[r0 + rlo] = dist1;
                }
                {
                    const u64 sc = fma2(bp, shi2p, zerop);
                    const u64 xy = fma2(yp, onep, xhip);
                    const u64 cp = pack2((float)c[mt][nt][2], (float)c[mt][nt][3]);
                    const u64 d2 = fma2(cp, sc, xy);
                    float d20, d21; unpack2(d2, d20, d21);
                    const float dist0 = sqa(fmaxf(d20, 0.f));
                    const float dist1 = sqa(fmaxf(d21, 0.f));
                    const float e0 = ex2a(dist0 * cexp);
                    const float e1 = ex2a(dist1 * cexp);
                    esum[mt][1] = fma2(pack2(e0, e1), onep, esum[mt][1]);
                    if (cg0 == lhi) g_dlbl[r0 + rhi] = dist0;
                    if (cg1 == lhi) g_dlbl[r0 + rhi] = dist1;
                }
            }
        }

        float esumf[4][2];
#pragma unroll
        for (int mt = 0; mt < 4; mt++)
#pragma unroll
            for (int h = 0; h < 2; h++) {
                float a, b; unpack2(esum[mt][h], a, b);
                float v = a + b;
                v += __shfl_xor_sync(0xffffffffu, v, 1);
                v += __shfl_xor_sync(0xffffffffu, v, 2);
                esumf[mt][h] = v;
            }
        if (t == 0) {
#pragma unroll
            for (int mt = 0; mt < 4; mt++) {
                rowsum[wm * 64 + mt * 16 + g][wn]     = esumf[mt][0];
                rowsum[wm * 64 + mt * 16 + g + 8][wn] = esumf[mt][1];
            }
        }
        __syncthreads();
        if (tid < BT) {
            float s = ((rowsum[tid][0] + rowsum[tid][1]) + rowsum[tid][2]) + rowsum[tid][3];
            g_part[tile & 31][r0 + tid] = s;
        }
        __syncthreads();   // protect shared metadata before next tile
    }
}

// ---------------- kernel 3: fused finalize + mean (single block, deterministic) ----------------
__global__ __launch_bounds__(1024, 1)
void final_kernel(const float* __restrict__ temp, float* __restrict__ out) {
    __shared__ float sh[1024];
    const int tid = threadIdx.x;
    const float invT = 1.0f / temp[0];
    float acc = 0.f;
#pragma unroll
    for (int r = 0; r < N / 1024; r++) {
        const int row = tid + r * 1024;
        float s = 0.f;
#pragma unroll
        for (int cidx = 0; cidx < M / BT; cidx++) s += g_part[cidx][row];
        acc += g_dlbl[row] * invT + __logf(s);
    }
    sh[tid] = acc;
    __syncthreads();
    for (int off = 512; off; off >>= 1) {
        if (tid < off) sh[tid] += sh[tid + off];
        __syncthreads();
    }
    if (tid == 0) out[0] = sh[0] / (float)N;
}

// ---------------- launch ----------------
extern "C" void kernel_launch(void* const* d_in, const int* in_sizes, int n_in,
                              void* d_out, int out_size) {
    const float* feat   = (const float*)d_in[0];
    const float* feat2  = (const float*)d_in[1];
    const void*  labels = d_in[2];
    const float* temp   = (const float*)d_in[3];
    float* out = (float*)d_out;

    static int attr_done = 0;
    if (!attr_done) {
        cudaFuncSetAttribute(gemm_kernel, cudaFuncAttributeMaxDynamicSharedMemorySize, SMEM_DYN);
        attr_done = 1;
    }

    quant_kernel<<<(N + M) / 8, 256>>>(feat, feat2, (const unsigned int*)labels);
    gemm_kernel<<<NPERS, 256, SMEM_DYN>>>(labels, temp);
    final_kernel<<<1, 1024>>>(temp, out);
}